// round 3
// baseline (speedup 1.0000x reference)
#include <cuda_runtime.h>
#include <math.h>

#define BB 16
#define NN 1024
#define CC 64
#define CIN 16
#define PADW 132   // padded width for 128-wide smem tiles
#define PADN 68    // padded width for 64-wide smem tiles

typedef unsigned long long u64;

__device__ __forceinline__ u64 splat2(float v) {
    u64 r; asm("mov.b64 %0, {%1, %1};" : "=l"(r) : "f"(v)); return r;
}
__device__ __forceinline__ void ffma2(u64& d, u64 a, u64 b) {
    asm("fma.rn.f32x2 %0, %1, %2, %0;" : "+l"(d) : "l"(a), "l"(b));
}
__device__ __forceinline__ float2 unpack2(u64 v) {
    float2 r; asm("mov.b64 {%0, %1}, %2;" : "=f"(r.x), "=f"(r.y) : "l"(v)); return r;
}

// ---------------- static device scratch ----------------
__device__ float g_att [BB*NN*NN];
__device__ float g_gl  [BB*NN*NN];   // unnormalized exp values
__device__ float g_g1  [NN*NN];
__device__ float g_g2  [NN*NN];
__device__ float g_d   [2*NN];
__device__ float g_h0a [BB*CC*NN];
__device__ float g_h0  [BB*CC*NN];
__device__ float g_hT  [BB*CC*NN];
__device__ float g_xatt[BB*CC*NN];
__device__ float g_xuai[BB*CC*NN];
__device__ float g_l12 [BB*2*CC*NN];
__device__ float g_t12 [BB*2*CC*NN];
__device__ float g_u12 [BB*2*CC*NN];
__device__ float g_a12 [BB*2*CC*NN];
__device__ float g_s12x[BB*2*CC*NN];
__device__ float g_s1  [BB*NN];
__device__ float g_s2  [BB*NN];
__device__ float g_sq  [BB*NN];
__device__ float g_rsinv[BB*NN];
__device__ float g_stats[2*BB*2];

// ---------------- laplacian prep ----------------
__global__ void k_lap_d(const float* __restrict__ graph) {
    int i = blockIdx.x, k = blockIdx.y, t = threadIdx.x;
    const float* row = graph + (size_t)k*NN*NN + (size_t)i*NN;
    float s = 0.f;
    for (int j = t; j < NN; j += 256) s += row[j];
    __shared__ float sh[256];
    sh[t] = s; __syncthreads();
    for (int o = 128; o > 0; o >>= 1) { if (t < o) sh[t] += sh[t+o]; __syncthreads(); }
    if (t == 0) g_d[k*NN + i] = rsqrtf(sh[0] + 1.0f);
}

__global__ void k_lap_scale(const float* __restrict__ graph) {
    __shared__ float tile[32][33];
    int k = blockIdx.z;
    int bx = blockIdx.x * 32, by = blockIdx.y * 32;
    const float* gsrc = graph + (size_t)k*NN*NN;
    for (int r = threadIdx.y; r < 32; r += 8) {
        int row = by + r, col = bx + threadIdx.x;
        float v = gsrc[(size_t)row*NN + col];
        if (row == col) v += 1.f;
        tile[r][threadIdx.x] = v;
    }
    __syncthreads();
    float* gout = (k == 0) ? g_g1 : g_g2;
    const float* d = g_d + k*NN;
    for (int r = threadIdx.y; r < 32; r += 8) {
        int a = bx + r, b_ = by + threadIdx.x;
        gout[(size_t)a*NN + b_] = tile[threadIdx.x][r] * d[a] * d[b_];
    }
}

// ---------------- embedding stage 1 ----------------
__global__ void k_emb1(const float* __restrict__ x, const float* __restrict__ emb_w,
                       const float* __restrict__ emb_b) {
    __shared__ float w[CC*CIN];
    __shared__ float bsm[CC];
    int t = threadIdx.x;
    for (int i = t; i < CC*CIN; i += 256) w[i] = emb_w[i];
    if (t < CC) bsm[t] = emb_b[t];
    __syncthreads();
    int b = blockIdx.x;
    int n = blockIdx.y * 256 + t;
    float xv[CIN];
    const float* xp = x + (size_t)b*CIN*NN + n;
#pragma unroll
    for (int c = 0; c < CIN; c++) xv[c] = xp[(size_t)c*NN];
    float* out = g_h0a + (size_t)b*CC*NN + n;
    for (int e = 0; e < CC; e++) {
        float s = bsm[e];
#pragma unroll
        for (int c = 0; c < CIN; c++) s = fmaf(w[e*CIN + c], xv[c], s);
        out[(size_t)e*NN] = (s > 0.f) ? s : 0.01f*s;
    }
}

// ================= gemm128: C[b, 0..127, n] = sum_k A[b,c,k] * G[k,n] * rs[k] ======
// block tile 128M x 128N, thread tile 8M x 8N, 256 threads, K-step 16 double-buffered.
__global__ void __launch_bounds__(256)
gemm128(const float* __restrict__ A, const float* __restrict__ G, size_t gStride,
        const float* __restrict__ rsinv, const float* __restrict__ addend,
        float* __restrict__ C) {
    const int b  = blockIdx.y;
    const int n0 = blockIdx.x * 128;
    const float* Ab = A + (size_t)b*(2*CC)*NN;
    const float* Gb = G + (size_t)b*gStride;
    const float* rs = rsinv ? rsinv + (size_t)b*NN : nullptr;
    __shared__ float As[2][16*PADW];
    __shared__ float Gs[2][16*PADW];
    const int tid = threadIdx.x;
    const int tx = tid & 15, ty = tid >> 4;

    const int ac = tid >> 1;
    const int ak = (tid & 1) * 8;
    const float* Aptr = Ab + (size_t)ac*NN + ak;
    const int gk = tid >> 4;
    const int gm = (tid & 15) * 8;
    const float* Gptr = Gb + (size_t)gk*NN + n0 + gm;

    float4 ra0 = *(const float4*)(Aptr);
    float4 ra1 = *(const float4*)(Aptr + 4);
    float4 rg0 = *(const float4*)(Gptr);
    float4 rg1 = *(const float4*)(Gptr + 4);
    float prs = rs ? rs[gk] : 1.f;
    {
        float* as = &As[0][ak*PADW + ac];
        as[0*PADW]=ra0.x; as[1*PADW]=ra0.y; as[2*PADW]=ra0.z; as[3*PADW]=ra0.w;
        as[4*PADW]=ra1.x; as[5*PADW]=ra1.y; as[6*PADW]=ra1.z; as[7*PADW]=ra1.w;
        float4 s0 = {rg0.x*prs, rg0.y*prs, rg0.z*prs, rg0.w*prs};
        float4 s1 = {rg1.x*prs, rg1.y*prs, rg1.z*prs, rg1.w*prs};
        *(float4*)&Gs[0][gk*PADW + gm] = s0;
        *(float4*)&Gs[0][gk*PADW + gm + 4] = s1;
    }
    __syncthreads();

    u64 acc[4][8] = {};
    for (int t = 0; t < 64; ++t) {
        int cur = t & 1;
        if (t < 63) {
            const float* ap = Aptr + (t+1)*16;
            ra0 = *(const float4*)(ap);
            ra1 = *(const float4*)(ap + 4);
            const float* gp = Gptr + (size_t)(t+1)*16*NN;
            rg0 = *(const float4*)(gp);
            rg1 = *(const float4*)(gp + 4);
            if (rs) prs = rs[(t+1)*16 + gk];
        }
#pragma unroll
        for (int kk = 0; kk < 16; kk++) {
            const float* arow = &As[cur][kk*PADW + ty*8];
            ulonglong2 av0 = *(const ulonglong2*)(arow);
            ulonglong2 av1 = *(const ulonglong2*)(arow + 4);
            const float* grow = &Gs[cur][kk*PADW + tx*8];
            float4 g0 = *(const float4*)(grow);
            float4 g1 = *(const float4*)(grow + 4);
            u64 gs[8];
            gs[0]=splat2(g0.x); gs[1]=splat2(g0.y); gs[2]=splat2(g0.z); gs[3]=splat2(g0.w);
            gs[4]=splat2(g1.x); gs[5]=splat2(g1.y); gs[6]=splat2(g1.z); gs[7]=splat2(g1.w);
#pragma unroll
            for (int j = 0; j < 8; j++) {
                ffma2(acc[0][j], av0.x, gs[j]);
                ffma2(acc[1][j], av0.y, gs[j]);
                ffma2(acc[2][j], av1.x, gs[j]);
                ffma2(acc[3][j], av1.y, gs[j]);
            }
        }
        if (t < 63) {
            int nxt = cur ^ 1;
            float* as = &As[nxt][ak*PADW + ac];
            as[0*PADW]=ra0.x; as[1*PADW]=ra0.y; as[2*PADW]=ra0.z; as[3*PADW]=ra0.w;
            as[4*PADW]=ra1.x; as[5*PADW]=ra1.y; as[6*PADW]=ra1.z; as[7*PADW]=ra1.w;
            float4 s0 = {rg0.x*prs, rg0.y*prs, rg0.z*prs, rg0.w*prs};
            float4 s1 = {rg1.x*prs, rg1.y*prs, rg1.z*prs, rg1.w*prs};
            *(float4*)&Gs[nxt][gk*PADW + gm] = s0;
            *(float4*)&Gs[nxt][gk*PADW + gm + 4] = s1;
        }
        __syncthreads();
    }

    float* Cb = C + (size_t)b*(2*CC)*NN + n0;
    const float* Db = addend ? addend + (size_t)b*(2*CC)*NN + n0 : nullptr;
#pragma unroll
    for (int i = 0; i < 4; i++) {
        int m = ty*8 + 2*i;
        float2 u[8];
#pragma unroll
        for (int j = 0; j < 8; j++) u[j] = unpack2(acc[i][j]);
        float4 lo0 = {u[0].x,u[1].x,u[2].x,u[3].x};
        float4 lo1 = {u[4].x,u[5].x,u[6].x,u[7].x};
        float4 hi0 = {u[0].y,u[1].y,u[2].y,u[3].y};
        float4 hi1 = {u[4].y,u[5].y,u[6].y,u[7].y};
        if (Db) {
            float4 d0 = *(const float4*)(Db + (size_t)m*NN + tx*8);
            float4 d1 = *(const float4*)(Db + (size_t)m*NN + tx*8 + 4);
            float4 d2 = *(const float4*)(Db + (size_t)(m+1)*NN + tx*8);
            float4 d3 = *(const float4*)(Db + (size_t)(m+1)*NN + tx*8 + 4);
            lo0.x+=d0.x; lo0.y+=d0.y; lo0.z+=d0.z; lo0.w+=d0.w;
            lo1.x+=d1.x; lo1.y+=d1.y; lo1.z+=d1.z; lo1.w+=d1.w;
            hi0.x+=d2.x; hi0.y+=d2.y; hi0.z+=d2.z; hi0.w+=d2.w;
            hi1.x+=d3.x; hi1.y+=d3.y; hi1.z+=d3.z; hi1.w+=d3.w;
        }
        *(float4*)(Cb + (size_t)m*NN + tx*8)       = lo0;
        *(float4*)(Cb + (size_t)m*NN + tx*8 + 4)   = lo1;
        *(float4*)(Cb + (size_t)(m+1)*NN + tx*8)     = hi0;
        *(float4*)(Cb + (size_t)(m+1)*NN + tx*8 + 4) = hi1;
    }
}

// ================= gemm64T: C[b,c,n] = sum_k A[b,c,k] * G[n,k] ====================
// G row-major [n][k]. block tile 64M x 128N, thread 8M x 4N, 256 threads.
template<int RELU>
__global__ void __launch_bounds__(256)
gemm64T(const float* __restrict__ A, const float* __restrict__ G, size_t gStride,
        const float* __restrict__ bias, float* __restrict__ C) {
    const int b  = blockIdx.y;
    const int n0 = blockIdx.x * 128;
    const float* Ab = A + (size_t)b*CC*NN;
    const float* Gb = G + (size_t)b*gStride;
    __shared__ float As[2][16*PADN];
    __shared__ float Gs[2][16*PADW];
    const int tid = threadIdx.x;
    const int tx = tid & 31, ty = tid >> 5;   // ty 0..7

    const int ar  = tid >> 2;
    const int akk = (tid & 3) * 4;
    const float* Aptr = Ab + (size_t)ar*NN + akk;
    const int gr  = tid >> 1;
    const int gkk = (tid & 1) * 8;
    const float* Gptr = Gb + (size_t)(n0 + gr)*NN + gkk;

    float4 ra  = *(const float4*)(Aptr);
    float4 rg0 = *(const float4*)(Gptr);
    float4 rg1 = *(const float4*)(Gptr + 4);
    {
        float* as = &As[0][akk*PADN + ar];
        as[0*PADN]=ra.x; as[1*PADN]=ra.y; as[2*PADN]=ra.z; as[3*PADN]=ra.w;
        float* gsp = &Gs[0][gkk*PADW + gr];
        gsp[0*PADW]=rg0.x; gsp[1*PADW]=rg0.y; gsp[2*PADW]=rg0.z; gsp[3*PADW]=rg0.w;
        gsp[4*PADW]=rg1.x; gsp[5*PADW]=rg1.y; gsp[6*PADW]=rg1.z; gsp[7*PADW]=rg1.w;
    }
    __syncthreads();

    u64 acc[4][4] = {};
    for (int t = 0; t < 64; ++t) {
        int cur = t & 1;
        if (t < 63) {
            ra  = *(const float4*)(Aptr + (t+1)*16);
            const float* gp = Gptr + (t+1)*16;
            rg0 = *(const float4*)(gp);
            rg1 = *(const float4*)(gp + 4);
        }
#pragma unroll
        for (int kk = 0; kk < 16; kk++) {
            const float* arow = &As[cur][kk*PADN + ty*8];
            ulonglong2 av0 = *(const ulonglong2*)(arow);
            ulonglong2 av1 = *(const ulonglong2*)(arow + 4);
            float4 g = *(const float4*)&Gs[cur][kk*PADW + tx*4];
            u64 gs0 = splat2(g.x), gs1 = splat2(g.y), gs2 = splat2(g.z), gs3 = splat2(g.w);
            ffma2(acc[0][0], av0.x, gs0); ffma2(acc[0][1], av0.x, gs1);
            ffma2(acc[0][2], av0.x, gs2); ffma2(acc[0][3], av0.x, gs3);
            ffma2(acc[1][0], av0.y, gs0); ffma2(acc[1][1], av0.y, gs1);
            ffma2(acc[1][2], av0.y, gs2); ffma2(acc[1][3], av0.y, gs3);
            ffma2(acc[2][0], av1.x, gs0); ffma2(acc[2][1], av1.x, gs1);
            ffma2(acc[2][2], av1.x, gs2); ffma2(acc[2][3], av1.x, gs3);
            ffma2(acc[3][0], av1.y, gs0); ffma2(acc[3][1], av1.y, gs1);
            ffma2(acc[3][2], av1.y, gs2); ffma2(acc[3][3], av1.y, gs3);
        }
        if (t < 63) {
            int nxt = cur ^ 1;
            float* as = &As[nxt][akk*PADN + ar];
            as[0*PADN]=ra.x; as[1*PADN]=ra.y; as[2*PADN]=ra.z; as[3*PADN]=ra.w;
            float* gsp = &Gs[nxt][gkk*PADW + gr];
            gsp[0*PADW]=rg0.x; gsp[1*PADW]=rg0.y; gsp[2*PADW]=rg0.z; gsp[3*PADW]=rg0.w;
            gsp[4*PADW]=rg1.x; gsp[5*PADW]=rg1.y; gsp[6*PADW]=rg1.z; gsp[7*PADW]=rg1.w;
        }
        __syncthreads();
    }

    float4 bv = {0.f,0.f,0.f,0.f};
    if (bias) bv = *(const float4*)(bias + n0 + tx*4);
    float* Cb = C + (size_t)b*CC*NN + n0;
#pragma unroll
    for (int i = 0; i < 4; i++) {
        int m = ty*8 + 2*i;
        float2 v0 = unpack2(acc[i][0]), v1 = unpack2(acc[i][1]);
        float2 v2 = unpack2(acc[i][2]), v3 = unpack2(acc[i][3]);
        float4 lo = {v0.x + bv.x, v1.x + bv.y, v2.x + bv.z, v3.x + bv.w};
        float4 hi = {v0.y + bv.x, v1.y + bv.y, v2.y + bv.z, v3.y + bv.w};
        if (RELU) {
            lo.x = fmaxf(lo.x, 0.f); lo.y = fmaxf(lo.y, 0.f);
            lo.z = fmaxf(lo.z, 0.f); lo.w = fmaxf(lo.w, 0.f);
            hi.x = fmaxf(hi.x, 0.f); hi.y = fmaxf(hi.y, 0.f);
            hi.z = fmaxf(hi.z, 0.f); hi.w = fmaxf(hi.w, 0.f);
        }
        *(float4*)(Cb + (size_t)m*NN + tx*4) = lo;
        *(float4*)(Cb + (size_t)(m+1)*NN + tx*4) = hi;
    }
}

// ---------------- 64x64 channel mix, dual-weight (grid.z selects) ----------------
// out[b, z*64+o, n] = sum_k W_z[o,k] * in[b, z*inZoff + k, n] + bias_z[o]
__global__ void __launch_bounds__(128)
chanmixD(const float* __restrict__ in, size_t inBstride, size_t inZoff,
         const float* __restrict__ Wa, const float* __restrict__ ba,
         const float* __restrict__ Wb, const float* __restrict__ bb_,
         int trans, float* __restrict__ out, size_t outBstride) {
    const int z = blockIdx.z;
    const float* W    = z ? Wb  : Wa;
    const float* bias = z ? bb_ : ba;
    const int b = blockIdx.y, n0 = blockIdx.x * 64;
    __shared__ float Ms[64*PADN];
    __shared__ float Xs[64*PADN];
    const int tid = threadIdx.x;
    // weights: Ms[k][o]
    for (int i = tid; i < 64*64; i += 128) {
        int o = i >> 6, k = i & 63;
        Ms[k*PADN + o] = trans ? W[k*64 + o] : W[o*64 + k];
    }
    const float* inb = in + (size_t)b*inBstride + (size_t)z*inZoff + n0;
    for (int i = tid; i < 64*16; i += 128) {
        int k = i >> 4, n4 = (i & 15) * 4;
        *(float4*)&Xs[k*PADN + n4] = *(const float4*)(inb + (size_t)k*NN + n4);
    }
    __syncthreads();
    const int tx = tid & 15, ty = tid >> 4;  // ty 0..7
    u64 acc[4][4] = {};
#pragma unroll 8
    for (int k = 0; k < 64; k++) {
        const float* mrow = &Ms[k*PADN + ty*8];
        ulonglong2 av0 = *(const ulonglong2*)(mrow);
        ulonglong2 av1 = *(const ulonglong2*)(mrow + 4);
        float4 xv = *(const float4*)&Xs[k*PADN + tx*4];
        u64 gs0 = splat2(xv.x), gs1 = splat2(xv.y), gs2 = splat2(xv.z), gs3 = splat2(xv.w);
        ffma2(acc[0][0], av0.x, gs0); ffma2(acc[0][1], av0.x, gs1);
        ffma2(acc[0][2], av0.x, gs2); ffma2(acc[0][3], av0.x, gs3);
        ffma2(acc[1][0], av0.y, gs0); ffma2(acc[1][1], av0.y, gs1);
        ffma2(acc[1][2], av0.y, gs2); ffma2(acc[1][3], av0.y, gs3);
        ffma2(acc[2][0], av1.x, gs0); ffma2(acc[2][1], av1.x, gs1);
        ffma2(acc[2][2], av1.x, gs2); ffma2(acc[2][3], av1.x, gs3);
        ffma2(acc[3][0], av1.y, gs0); ffma2(acc[3][1], av1.y, gs1);
        ffma2(acc[3][2], av1.y, gs2); ffma2(acc[3][3], av1.y, gs3);
    }
    float* outb = out + (size_t)b*outBstride + (size_t)z*CC*NN + n0;
#pragma unroll
    for (int i = 0; i < 4; i++) {
        int o = ty*8 + 2*i;
        float b0 = bias ? bias[o]   : 0.f;
        float b1 = bias ? bias[o+1] : 0.f;
        float2 v0 = unpack2(acc[i][0]), v1 = unpack2(acc[i][1]);
        float2 v2 = unpack2(acc[i][2]), v3 = unpack2(acc[i][3]);
        float4 lo = {v0.x + b0, v1.x + b0, v2.x + b0, v3.x + b0};
        float4 hi = {v0.y + b1, v1.y + b1, v2.y + b1, v3.y + b1};
        *(float4*)(outb + (size_t)o*NN + tx*4) = lo;
        *(float4*)(outb + (size_t)(o+1)*NN + tx*4) = hi;
    }
}

// ---------------- attention scores (rank-1) ----------------
__global__ void k_s12(const float* __restrict__ att_a) {
    __shared__ float a1[64], a2[64];
    int t = threadIdx.x;
    if (t < 64) a1[t] = att_a[t];
    else if (t < 128) a2[t-64] = att_a[t];
    __syncthreads();
    int b = blockIdx.x;
    int i = blockIdx.y * 256 + t;
    const float* h = g_hT + (size_t)b*CC*NN + i;
    float v1 = 0.f, v2 = 0.f;
#pragma unroll 8
    for (int c = 0; c < 64; c++) {
        float hv = h[(size_t)c*NN];
        v1 = fmaf(hv, a1[c], v1);
        v2 = fmaf(hv, a2[c], v2);
    }
    g_s1[b*NN + i] = v1;
    g_s2[b*NN + i] = v2;
}

__global__ void k_attrow() {
    int b = blockIdx.y, i = blockIdx.x, t = threadIdx.x;
    float s1 = g_s1[b*NN + i];
    const float* s2 = g_s2 + b*NN;
    float v[4];
    float mx = -1e30f;
#pragma unroll
    for (int q = 0; q < 4; q++) {
        float e = s1 + s2[t + 256*q];
        e = (e > 0.f) ? e : 0.01f*e;
        v[q] = e;
        mx = fmaxf(mx, e);
    }
    __shared__ float sh[256];
    sh[t] = mx; __syncthreads();
    for (int o = 128; o > 0; o >>= 1) { if (t < o) sh[t] = fmaxf(sh[t], sh[t+o]); __syncthreads(); }
    mx = sh[0]; __syncthreads();
    float sm = 0.f;
#pragma unroll
    for (int q = 0; q < 4; q++) { v[q] = __expf(v[q] - mx); sm += v[q]; }
    sh[t] = sm; __syncthreads();
    for (int o = 128; o > 0; o >>= 1) { if (t < o) sh[t] += sh[t+o]; __syncthreads(); }
    float inv = 1.f / sh[0];
    float* arow = g_att + ((size_t)b*NN + i)*NN;
#pragma unroll
    for (int q = 0; q < 4; q++) arow[t + 256*q] = v[q] * inv;
}

// ---------------- learned adjacency (gram + rbf) ----------------
__global__ void k_sq() {
    int b = blockIdx.x, n = blockIdx.y * 256 + threadIdx.x;
    const float* xp = g_xuai + (size_t)b*CC*NN + n;
    float s = 0.f;
#pragma unroll 8
    for (int c = 0; c < CC; c++) { float v = xp[(size_t)c*NN]; s = fmaf(v, v, s); }
    g_sq[b*NN + n] = s;
}

// gl_un[b,i,j] = exp( exp(-max(sq_i+sq_j-2*P_ij,0)/128) + (i==j) )
__global__ void __launch_bounds__(128)
k_gram() {
    int b = blockIdx.z;
    int i0 = blockIdx.x * 64, j0 = blockIdx.y * 64;
    __shared__ float Xi[64*PADN], Xj[64*PADN];
    const float* X = g_xuai + (size_t)b*CC*NN;
    int tid = threadIdx.x;
    for (int p = tid; p < 64*16; p += 128) {
        int c = p >> 4, q4 = (p & 15) * 4;
        *(float4*)&Xi[c*PADN + q4] = *(const float4*)(X + (size_t)c*NN + i0 + q4);
        *(float4*)&Xj[c*PADN + q4] = *(const float4*)(X + (size_t)c*NN + j0 + q4);
    }
    __syncthreads();
    const int tx = tid & 15, ty = tid >> 4;
    u64 acc[4][4] = {};
#pragma unroll 8
    for (int c = 0; c < 64; c++) {
        const float* irow = &Xi[c*PADN + ty*8];
        ulonglong2 av0 = *(const ulonglong2*)(irow);
        ulonglong2 av1 = *(const ulonglong2*)(irow + 4);
        float4 xv = *(const float4*)&Xj[c*PADN + tx*4];
        u64 gs0 = splat2(xv.x), gs1 = splat2(xv.y), gs2 = splat2(xv.z), gs3 = splat2(xv.w);
        ffma2(acc[0][0], av0.x, gs0); ffma2(acc[0][1], av0.x, gs1);
        ffma2(acc[0][2], av0.x, gs2); ffma2(acc[0][3], av0.x, gs3);
        ffma2(acc[1][0], av0.y, gs0); ffma2(acc[1][1], av0.y, gs1);
        ffma2(acc[1][2], av0.y, gs2); ffma2(acc[1][3], av0.y, gs3);
        ffma2(acc[2][0], av1.x, gs0); ffma2(acc[2][1], av1.x, gs1);
        ffma2(acc[2][2], av1.x, gs2); ffma2(acc[2][3], av1.x, gs3);
        ffma2(acc[3][0], av1.y, gs0); ffma2(acc[3][1], av1.y, gs1);
        ffma2(acc[3][2], av1.y, gs2); ffma2(acc[3][3], av1.y, gs3);
    }
    const float* sq = g_sq + b*NN;
    float* glb = g_gl + (size_t)b*NN*NN;
#pragma unroll
    for (int p = 0; p < 4; p++) {
        int i = i0 + ty*8 + 2*p;
        float sqa = sq[i], sqb = sq[i+1];
        float2 v0 = unpack2(acc[p][0]), v1 = unpack2(acc[p][1]);
        float2 v2 = unpack2(acc[p][2]), v3 = unpack2(acc[p][3]);
        float pr0[4] = {v0.x, v1.x, v2.x, v3.x};
        float pr1[4] = {v0.y, v1.y, v2.y, v3.y};
        float4 o0, o1;
        float* po0 = &o0.x; float* po1 = &o1.x;
#pragma unroll
        for (int q = 0; q < 4; q++) {
            int j = j0 + tx*4 + q;
            float d2a = fmaxf(sqa + sq[j] - 2.f*pr0[q], 0.f);
            float ma = __expf(-d2a * (1.f/128.f)) + ((i == j) ? 1.f : 0.f);
            po0[q] = __expf(ma);
            float d2b = fmaxf(sqb + sq[j] - 2.f*pr1[q], 0.f);
            float mb = __expf(-d2b * (1.f/128.f)) + ((i+1 == j) ? 1.f : 0.f);
            po1[q] = __expf(mb);
        }
        *(float4*)(glb + (size_t)i*NN + j0 + tx*4) = o0;
        *(float4*)(glb + (size_t)(i+1)*NN + j0 + tx*4) = o1;
    }
}

__global__ void k_rowsuminv() {
    int b = blockIdx.y, i = blockIdx.x, t = threadIdx.x;
    const float* row = g_gl + ((size_t)b*NN + i)*NN;
    float s = 0.f;
#pragma unroll
    for (int q = 0; q < 4; q++) s += row[t + 256*q];
    __shared__ float sh[256];
    sh[t] = s; __syncthreads();
    for (int o = 128; o > 0; o >>= 1) { if (t < o) sh[t] += sh[t+o]; __syncthreads(); }
    if (t == 0) g_rsinv[b*NN + i] = 1.f / sh[0];
}

// ---------------- layernorm stats + final fuse ----------------
__global__ void k_lnstats() {
    int b = blockIdx.x, path = blockIdx.y, t = threadIdx.x;
    const float* z = g_s12x + (size_t)b*(2*CC)*NN + (size_t)path*CC*NN;
    float s = 0.f, ss = 0.f;
    for (int i = t; i < CC*NN; i += 1024) { float v = z[i]; s += v; ss = fmaf(v, v, ss); }
    __shared__ float shs[1024], shq[1024];
    shs[t] = s; shq[t] = ss; __syncthreads();
    for (int o = 512; o > 0; o >>= 1) {
        if (t < o) { shs[t] += shs[t+o]; shq[t] += shq[t+o]; }
        __syncthreads();
    }
    if (t == 0) {
        float mean = shs[0] * (1.f/65536.f);
        float var  = shq[0] * (1.f/65536.f) - mean*mean;
        g_stats[(path*BB + b)*2 + 0] = mean;
        g_stats[(path*BB + b)*2 + 1] = rsqrtf(var + 1e-5f);
    }
}

__global__ void k_final(const float* __restrict__ ct, const float* __restrict__ ln_w,
                        const float* __restrict__ ln_b, float* __restrict__ out) {
    size_t idx = (size_t)blockIdx.x * 256 + threadIdx.x;
    int b  = (int)(idx / (CC*NN));
    int cn = (int)(idx % (CC*NN));
    float m1 = g_stats[b*2 + 0],            r1 = g_stats[b*2 + 1];
    float m2 = g_stats[(BB + b)*2 + 0],     r2 = g_stats[(BB + b)*2 + 1];
    float w = ln_w[cn], bb = ln_b[cn];
    size_t base = (size_t)b*(2*CC)*NN + cn;
    float xnew = (g_s12x[base]                 - m1) * r1 * w + bb;
    float z2   = (g_s12x[base + (size_t)CC*NN] - m2) * r2 * w + bb;
    float ft = 0.5f * z2 * (1.f + erff(z2 * 0.70710678118654752f));
    float ctv = ct[idx];
    float ctn = xnew + ft * (ctv - xnew);
    float el  = (ctn > 0.f) ? ctn : expm1f(ctn);
    float xu  = g_xuai[idx];
    float ht  = xu + ft * (el - xu);
    out[idx] = ht;
    out[(size_t)BB*CC*NN + idx] = ctn;
}

// ---------------- host launch ----------------
struct DevPtrs {
    float *att, *gl, *g1, *g2, *h0a, *h0, *hT, *xatt, *xuai;
    float *l12, *t12, *u12, *a12, *s12x, *rsinv;
    bool init;
};
static DevPtrs P = {};

static void init_ptrs() {
    if (P.init) return;
    void* p;
#define GET(sym, field) cudaGetSymbolAddress(&p, sym); P.field = (float*)p;
    GET(g_att, att)  GET(g_gl, gl)   GET(g_g1, g1)   GET(g_g2, g2)
    GET(g_h0a, h0a)  GET(g_h0, h0)   GET(g_hT, hT)   GET(g_xatt, xatt)
    GET(g_xuai, xuai) GET(g_l12, l12) GET(g_t12, t12) GET(g_u12, u12)
    GET(g_a12, a12)  GET(g_s12x, s12x) GET(g_rsinv, rsinv)
#undef GET
    P.init = true;
}

extern "C" void kernel_launch(void* const* d_in, const int* in_sizes, int n_in,
                              void* d_out, int out_size) {
    const float* x      = (const float*)d_in[0];
    const float* ct     = (const float*)d_in[1];
    const float* graph  = (const float*)d_in[2];
    const float* emb_w  = (const float*)d_in[3];
    const float* emb_b  = (const float*)d_in[4];
    const float* emb2_w = (const float*)d_in[5];
    const float* emb2_b = (const float*)d_in[6];
    const float* att_W  = (const float*)d_in[7];
    const float* att_a  = (const float*)d_in[8];
    // d_in[9] = att_GL : unused (softmax output strictly positive => mask no-op)
    const float* uai_w  = (const float*)d_in[10];
    const float* uai_b  = (const float*)d_in[11];
    const float* lin1_w = (const float*)d_in[12];
    const float* lin2_w = (const float*)d_in[13];
    const float* lin2_b = (const float*)d_in[14];
    const float* ln_w   = (const float*)d_in[15];
    const float* ln_b   = (const float*)d_in[16];
    float* out = (float*)d_out;

    init_ptrs();

    const dim3 gridG(NN/128, BB);       // 8 x 16 for big GEMMs
    const dim3 gridC1(NN/64, BB, 1);    // chanmix single
    const dim3 gridC2(NN/64, BB, 2);    // chanmix dual
    const size_t GSTRIDE = (size_t)NN * NN;
    const size_t SB = (size_t)CC*NN;
    const size_t DB = (size_t)2*CC*NN;

    // graph laplacians
    k_lap_d    <<<dim3(NN, 2), 256>>>(graph);
    k_lap_scale<<<dim3(32, 32, 2), dim3(32, 8)>>>(graph);

    // embedding
    k_emb1<<<dim3(BB, NN/256), 256>>>(x, emb_w, emb_b);
    gemm64T<0><<<gridG, 256>>>(P.h0a, emb2_w, 0, emb2_b, P.h0);

    // attention
    chanmixD<<<gridC1, 128>>>(P.h0, SB, 0, att_W, nullptr, att_W, nullptr, 1, P.hT, SB);
    k_s12   <<<dim3(BB, NN/256), 256>>>(att_a);
    k_attrow<<<dim3(NN, BB), 256>>>();
    gemm64T<1><<<gridG, 256>>>(P.hT, P.att, GSTRIDE, nullptr, P.xatt);

    // UAI linear
    chanmixD<<<gridC1, 128>>>(P.xatt, SB, 0, uai_w, uai_b, uai_w, uai_b, 0, P.xuai, SB);

    // learned adjacency gl (unnormalized) + row-sum inverses
    k_sq       <<<dim3(BB, NN/256), 256>>>();
    k_gram     <<<dim3(16, 16, BB), 128>>>();
    k_rowsuminv<<<dim3(NN, BB), 256>>>();

    // l1/l2 stacked propagation
    chanmixD<<<gridC2, 128>>>(P.xuai, SB, 0, lin1_w, nullptr, lin2_w, lin2_b, 0, P.l12, DB);

    gemm128<<<gridG, 256>>>(P.l12, P.gl, GSTRIDE, P.rsinv, nullptr, P.a12);
    gemm128<<<gridG, 256>>>(P.l12, P.g1, 0, nullptr, nullptr, P.t12);

    chanmixD<<<gridC2, 128>>>(P.t12, DB, SB, lin1_w, nullptr, lin2_w, lin2_b, 0, P.u12, DB);

    gemm128<<<gridG, 256>>>(P.u12, P.g2, 0, nullptr, P.a12, P.s12x);

    // layernorm + gates + output
    k_lnstats<<<dim3(BB, 2), 1024>>>();
    k_final  <<<(BB*CC*NN)/256, 256>>>(ct, ln_w, ln_b, out);
}